// round 11
// baseline (speedup 1.0000x reference)
#include <cuda_runtime.h>
#include <cuda_bf16.h>

// Problem shape (fixed by the dataset)
#define B_DIM 16
#define S_DIM 2048
#define D_DIM 256
#define ROWS  (B_DIM * S_DIM)          // 32768
#define QUADS (ROWS / 4)               // 8192
#define P_ASEM 0.6f
#define Q_ASEM 0.4f
#define MASK_FILL 1e-9f

// Scratch for projected scores (no cudaMalloc allowed)
__device__ float g_si[ROWS];  // si + bias folded in
__device__ float g_sj[ROWS];

// ---------------------------------------------------------------------------
// Kernel 1 (proj_fill): quad per block (8192 blocks).
//   - ALL threads: write MASK_FILL rows of the output for masked rows
//     (134 MB of writes that don't depend on the projections).
//   - warps 0..3: compute the dual dot products for their (unmasked) row.
// ---------------------------------------------------------------------------
__global__ __launch_bounds__(256) void proj_fill_kernel(const float* __restrict__ x,
                                                        const int*   __restrict__ mask,
                                                        const float* __restrict__ W,
                                                        const float* __restrict__ bias,
                                                        float4*      __restrict__ out4) {
    const unsigned tid  = threadIdx.x;
    const int      lane = tid & 31;
    const int      wid  = tid >> 5;
    const unsigned row0 = blockIdx.x << 2;
    const unsigned base = row0 << 9;

    int mi[4];
#pragma unroll
    for (int r = 0; r < 4; ++r) mi[r] = __ldg(&mask[row0 + r]);

    // ---- projections for unmasked rows (warps 0..3, one row each) ----
    if (wid < 4 && mi[wid]) {
        const int row = row0 + wid;
        const float4* x4  = reinterpret_cast<const float4*>(x) + (long)row * (D_DIM / 4);
        const float4* Wi4 = reinterpret_cast<const float4*>(W);            // W[0:256]
        const float4* Wj4 = reinterpret_cast<const float4*>(W + D_DIM);    // W[256:512]

        float4 xv0 = x4[lane];
        float4 xv1 = x4[lane + 32];
        float4 wi0 = __ldg(&Wi4[lane]);
        float4 wi1 = __ldg(&Wi4[lane + 32]);
        float4 wj0 = __ldg(&Wj4[lane]);
        float4 wj1 = __ldg(&Wj4[lane + 32]);

        float si = 0.f, sj = 0.f;
        si = fmaf(xv0.x, wi0.x, si); si = fmaf(xv0.y, wi0.y, si);
        si = fmaf(xv0.z, wi0.z, si); si = fmaf(xv0.w, wi0.w, si);
        si = fmaf(xv1.x, wi1.x, si); si = fmaf(xv1.y, wi1.y, si);
        si = fmaf(xv1.z, wi1.z, si); si = fmaf(xv1.w, wi1.w, si);
        sj = fmaf(xv0.x, wj0.x, sj); sj = fmaf(xv0.y, wj0.y, sj);
        sj = fmaf(xv0.z, wj0.z, sj); sj = fmaf(xv0.w, wj0.w, sj);
        sj = fmaf(xv1.x, wj1.x, sj); sj = fmaf(xv1.y, wj1.y, sj);
        sj = fmaf(xv1.z, wj1.z, sj); sj = fmaf(xv1.w, wj1.w, sj);

#pragma unroll
        for (int off = 16; off > 0; off >>= 1) {
            si += __shfl_down_sync(0xFFFFFFFFu, si, off);
            sj += __shfl_down_sync(0xFFFFFFFFu, sj, off);
        }
        if (lane == 0) {
            g_si[row] = si + __ldg(bias);
            g_sj[row] = sj;
        }
    }

    // ---- fill writes for masked rows (all 256 threads) ----
    const float4 fill = make_float4(MASK_FILL, MASK_FILL, MASK_FILL, MASK_FILL);
#pragma unroll
    for (int r = 0; r < 4; ++r) {
        if (!mi[r]) {
            const unsigned o = base + (r << 9) + tid;
            __stcs(&out4[o], fill);
            __stcs(&out4[o + 256], fill);
        }
    }
}

// ---------------------------------------------------------------------------
// Kernel 2 (blend): exact R6 fuse body, masked-row branch removed (those rows
// were already written by proj_fill). Blocks with no unmasked rows exit.
// ---------------------------------------------------------------------------
__device__ __forceinline__ float sig_blend(float si, float sjv, int m, float a) {
    float z = si + sjv;
    float s = __fdividef(1.f, 1.f + __expf(-z));
    return m ? fmaf(P_ASEM, s, Q_ASEM * a) : MASK_FILL;
}

__global__ __launch_bounds__(256) void blend_kernel(const float4* __restrict__ adj4,
                                                    const int*    __restrict__ mask,
                                                    float4*       __restrict__ out4) {
    const unsigned tid   = threadIdx.x;
    const unsigned row0  = blockIdx.x << 2;                  // 4 rows, same batch
    const unsigned base  = row0 << 9;                        // first float4 of the block
    const unsigned cbase = ((row0 >> 11) << 9) + tid;        // sj/mask col float4 index

    int mi[4];
#pragma unroll
    for (int r = 0; r < 4; ++r) mi[r] = mask[row0 + r];

    if (!(mi[0] | mi[1] | mi[2] | mi[3])) return;            // whole quad masked

    // issue ALL adj loads for unmasked rows up front (predicated, independent)
    float4 aA[4], aB[4];
#pragma unroll
    for (int r = 0; r < 4; ++r) {
        if (mi[r]) {
            const unsigned o = base + (r << 9) + tid;
            aA[r] = __ldcs(&adj4[o]);
            aB[r] = __ldcs(&adj4[o + 256]);
        }
    }

    // column vectors: shared by all 4 rows, loaded once
    const float4* sj4 = reinterpret_cast<const float4*>(g_sj);
    const int4*   mj4 = reinterpret_cast<const int4*>(mask);
    const float4 sjA = __ldg(&sj4[cbase]);
    const float4 sjB = __ldg(&sj4[cbase + 256]);
    const int4   mA  = __ldg(&mj4[cbase]);
    const int4   mB  = __ldg(&mj4[cbase + 256]);

#pragma unroll
    for (int r = 0; r < 4; ++r) {
        if (mi[r]) {
            const unsigned o  = base + (r << 9) + tid;
            const float    si = g_si[row0 + r];
            float4 out;
            out.x = sig_blend(si, sjA.x, mA.x, aA[r].x);
            out.y = sig_blend(si, sjA.y, mA.y, aA[r].y);
            out.z = sig_blend(si, sjA.z, mA.z, aA[r].z);
            out.w = sig_blend(si, sjA.w, mA.w, aA[r].w);
            __stcs(&out4[o], out);

            out.x = sig_blend(si, sjB.x, mB.x, aB[r].x);
            out.y = sig_blend(si, sjB.y, mB.y, aB[r].y);
            out.z = sig_blend(si, sjB.z, mB.z, aB[r].z);
            out.w = sig_blend(si, sjB.w, mB.w, aB[r].w);
            __stcs(&out4[o + 256], out);
        }
    }
}

// ---------------------------------------------------------------------------
// Launch
// Inputs (metadata order): 0:x [16,2048,256] f32, 1:adj [16,2048,2048] f32,
//                          2:mask [16,2048] i32, 3:W [1,512] f32, 4:b [1] f32
// Output: [16,2048,2048] f32
// ---------------------------------------------------------------------------
extern "C" void kernel_launch(void* const* d_in, const int* in_sizes, int n_in,
                              void* d_out, int out_size) {
    const float* x    = (const float*)d_in[0];
    const float* adj  = (const float*)d_in[1];
    const int*   mask = (const int*)d_in[2];
    const float* W    = (const float*)d_in[3];
    const float* bias = (const float*)d_in[4];
    float4* out = (float4*)d_out;

    // Kernel 1: projections + masked-row fill (quad per block)
    proj_fill_kernel<<<QUADS, 256>>>(x, mask, W, bias, out);

    // Kernel 2: blend for unmasked rows only
    blend_kernel<<<QUADS, 256>>>(reinterpret_cast<const float4*>(adj),
                                 mask, out);
}